// round 17
// baseline (speedup 1.0000x reference)
#include <cuda_runtime.h>
#include <math.h>

#define D 128
#define MAXN 10000
#define STRIDE 128               // bucket capacity per node (deg ~ 64 ± 8)

// Scratch (no allocation allowed -> __device__ globals)
// g_cursor is restored to 0 by mega_kernel (zero-init at load).
__device__ float  g_deginv[MAXN];
__device__ int    g_cursor[MAXN];
__device__ __align__(16) int2 g_edge[MAXN * STRIDE]; // {src, ew_bits}

// ---------------------------------------------------------------------------
// Pass 1: fill strided buckets, 2 edges per thread (grid 2x larger than the
// 4/thread version -> ~2x resident warps -> ~2x in-flight atomics).
// Cursor doubles as the in-degree counter.
// ---------------------------------------------------------------------------
__global__ void fill_kernel(const int* __restrict__ ei,
                            const float* __restrict__ ew,
                            int E) {
    int i = blockIdx.x * blockDim.x + threadIdx.x;
    int e = i * 2;
    if (e + 1 < E) {
        int2   s2 = *reinterpret_cast<const int2*>(ei + e);
        int2   d2 = *reinterpret_cast<const int2*>(ei + E + e);
        float2 w2 = *reinterpret_cast<const float2*>(ew + e);
        int p0 = atomicAdd(&g_cursor[d2.x], 1);
        int p1 = atomicAdd(&g_cursor[d2.y], 1);
        g_edge[(d2.x << 7) + p0] = make_int2(s2.x, __float_as_int(w2.x));
        g_edge[(d2.y << 7) + p1] = make_int2(s2.y, __float_as_int(w2.y));
    } else if (e < E) {
        int src = ei[e];
        int dst = ei[E + e];
        int pos = atomicAdd(&g_cursor[dst], 1);
        g_edge[(dst << 7) + pos] = make_int2(src, __float_as_int(ew[e]));
    }
}

// ---------------------------------------------------------------------------
// Pass 2: deginv = rsqrt(cursor + 1)   (cursor == deg after fill)
// ---------------------------------------------------------------------------
__global__ void deginv_kernel(int N) {
    int i = blockIdx.x * blockDim.x + threadIdx.x;
    if (i < N) g_deginv[i] = rsqrtf((float)g_cursor[i] + 1.0f);
}

// ---------------------------------------------------------------------------
// Pass 3: mega kernel.
//  Phase 1: warp w gathers row row0+w (R11-proven loop).  Result written
//           TRANSPOSED into s_aT[k][row] (pad 12 -> 16B-aligned float4 at
//           row offsets 0 and 4; write conflicts are once-per-row, cheap).
//  Phase 2: GEMM: per k: 1 LDG.32 (W) + 1 LDS.128 broadcast (4 rows' a[k])
//           + 4 FFMA  (6 inst/k vs 9 in the 4x LDS.32 version).
//  Phase 3: GELU + LN (block partials in smem).
// ---------------------------------------------------------------------------
__global__ void mega_kernel(const float* __restrict__ x,
                            const float* __restrict__ W,
                            const float* __restrict__ b,
                            const float* __restrict__ gamma,
                            const float* __restrict__ beta,
                            float* __restrict__ out,
                            int N) {
    __shared__ float s_aT[D][12];    // [k][row] ; cols 8..11 unused padding
    __shared__ int   s_src[8][32];
    __shared__ float s_cf[8][32];
    __shared__ float s_sum[8][4];
    __shared__ float s_sq[8][4];

    const int tid  = threadIdx.x;
    const int wid  = tid >> 5;
    const int lane = tid & 31;
    const int row0 = blockIdx.x * 8;
    const float4* xp = reinterpret_cast<const float4*>(x);

    // ---- Phase 1: gather own row ----
    {
        const int row = row0 + wid;
        float4 res = make_float4(0.f, 0.f, 0.f, 0.f);

        if (row < N) {
            const int bkt  = row << 7;
            const int dcnt = g_cursor[row];
            __syncwarp();
            if (lane == 0) g_cursor[row] = 0;   // restore invariant

            float4 acc = make_float4(0.f, 0.f, 0.f, 0.f);

            for (int base = 0; base < dcnt; base += 32) {
                int idx = base + lane;
                if (idx < dcnt) {
                    int2 em = g_edge[bkt + idx];
                    s_src[wid][lane] = em.x;
                    s_cf[wid][lane]  = g_deginv[em.x] * __int_as_float(em.y);
                }
                __syncwarp();

                int m = dcnt - base;
                if (m >= 32) {
                    #pragma unroll
                    for (int k = 0; k < 32; k++) {
                        int   s = s_src[wid][k];
                        float c = s_cf[wid][k];
                        float4 v = xp[(size_t)s * 32 + lane];
                        acc.x += v.x * c; acc.y += v.y * c;
                        acc.z += v.z * c; acc.w += v.w * c;
                    }
                } else {
                    for (int k = 0; k < m; k++) {
                        int   s = s_src[wid][k];
                        float c = s_cf[wid][k];
                        float4 v = xp[(size_t)s * 32 + lane];
                        acc.x += v.x * c; acc.y += v.y * c;
                        acc.z += v.z * c; acc.w += v.w * c;
                    }
                }
                __syncwarp();
            }

            float di = g_deginv[row];
            float4 xr = xp[(size_t)row * 32 + lane];
            res.x = acc.x * di + xr.x;
            res.y = acc.y * di + xr.y;
            res.z = acc.z * di + xr.z;
            res.w = acc.w * di + xr.w;
        }

        // transposed store: lane l owns cols 4l..4l+3 of row (row0+wid)
        s_aT[4 * lane + 0][wid] = res.x;
        s_aT[4 * lane + 1][wid] = res.y;
        s_aT[4 * lane + 2][wid] = res.z;
        s_aT[4 * lane + 3][wid] = res.w;
    }
    __syncthreads();

    // ---- Phase 2: GEMM ----
    const int col  = tid & 127;
    const int half = tid >> 7;
    const int r0   = half * 4;

    float acc0 = b[col], acc1 = acc0, acc2 = acc0, acc3 = acc0;

    #pragma unroll 8
    for (int k = 0; k < D; k++) {
        float  w  = W[k * D + col];
        float4 a4 = *reinterpret_cast<const float4*>(&s_aT[k][r0]);
        acc0 += a4.x * w;
        acc1 += a4.y * w;
        acc2 += a4.z * w;
        acc3 += a4.w * w;
    }

    float h[4] = {acc0, acc1, acc2, acc3};

    // exact gelu
    #pragma unroll
    for (int r = 0; r < 4; r++) {
        float v = h[r];
        h[r] = 0.5f * v * (1.0f + erff(v * 0.70710678118654752f));
    }

    // ---- Phase 3: LayerNorm ----
    float sum[4], sq[4];
    #pragma unroll
    for (int r = 0; r < 4; r++) { sum[r] = h[r]; sq[r] = h[r] * h[r]; }

    #pragma unroll
    for (int off = 16; off > 0; off >>= 1) {
        #pragma unroll
        for (int r = 0; r < 4; r++) {
            sum[r] += __shfl_xor_sync(0xFFFFFFFF, sum[r], off);
            sq[r]  += __shfl_xor_sync(0xFFFFFFFF, sq[r], off);
        }
    }
    const int wih = (tid >> 5) & 3;
    if (lane == 0) {
        #pragma unroll
        for (int r = 0; r < 4; r++) {
            s_sum[r0 + r][wih] = sum[r];
            s_sq[r0 + r][wih]  = sq[r];
        }
    }
    __syncthreads();

    float g = gamma[col], bt = beta[col];
    #pragma unroll
    for (int r = 0; r < 4; r++) {
        int rr = r0 + r;
        float s = s_sum[rr][0] + s_sum[rr][1] + s_sum[rr][2] + s_sum[rr][3];
        float q = s_sq[rr][0]  + s_sq[rr][1]  + s_sq[rr][2]  + s_sq[rr][3];
        float mu  = s * (1.0f / D);
        float var = q * (1.0f / D) - mu * mu;
        float rstd = rsqrtf(var + 1e-5f);
        int row = row0 + rr;
        if (row < N) {
            out[(size_t)row * D + col] = (h[r] - mu) * rstd * g + bt;
        }
    }
}

// ---------------------------------------------------------------------------
// Launch
// Inputs (metadata order): x, edge_index(int32), edge_weight, W, b, gamma, beta
// ---------------------------------------------------------------------------
extern "C" void kernel_launch(void* const* d_in, const int* in_sizes, int n_in,
                              void* d_out, int out_size) {
    const float* x     = (const float*)d_in[0];
    const int*   ei    = (const int*)d_in[1];
    const float* ew    = (const float*)d_in[2];
    const float* W     = (const float*)d_in[3];
    const float* b     = (const float*)d_in[4];
    const float* gamma = (const float*)d_in[5];
    const float* beta  = (const float*)d_in[6];
    float*       out   = (float*)d_out;

    const int N = in_sizes[0] / D;       // 10000
    const int E = in_sizes[2];           // 640000

    int e2 = (E + 1) / 2;
    fill_kernel<<<(e2 + 255) / 256, 256>>>(ei, ew, E);
    deginv_kernel<<<(N + 255) / 256, 256>>>(N);
    mega_kernel<<<(N + 7) / 8, 256>>>(x, W, b, gamma, beta, out, N);
}